// round 2
// baseline (speedup 1.0000x reference)
#include <cuda_runtime.h>
#include <cstdint>

// Problem constants
#define Bz 4
#define Sz 2048
#define Ez 1024
#define Hz 16
#define Dz 64
#define Mrows (Bz*Sz)          // 8192
#define FF (4*Ez)              // 4096

// ---------------------------------------------------------------------------
// Scratch (allocation-free: __device__ globals)
// ---------------------------------------------------------------------------
__device__ float g_Q[(size_t)Mrows*Ez];
__device__ float g_K[(size_t)Mrows*Ez];
__device__ float g_V[(size_t)Mrows*Ez];
__device__ float g_ATT[(size_t)Mrows*Ez];
__device__ float g_X1[(size_t)Mrows*Ez];
__device__ float g_Hb[(size_t)Mrows*FF];

// ---------------------------------------------------------------------------
// Tiled SGEMM: C[M,N] = A[M,K] @ B[K,N]  (+ optional epilogues)
// HEADED: B is stored [H, K, 64] and logical column n = h*64+d
// EPI: 0 = none, 1 = +bias then ReLU, 2 = +bias +res (residual, same shape as C)
// BM=BN=128, BK=8, 256 threads, 8x8 per-thread tile.
// ---------------------------------------------------------------------------
#define BM 128
#define BN 128
#define BK 8
#define TM 8
#define TN 8

template<bool HEADED, int EPI>
__global__ void __launch_bounds__(256)
sgemm_kernel(const float* __restrict__ A, const float* __restrict__ Bm,
             const float* __restrict__ bias, const float* __restrict__ res,
             float* __restrict__ C, int M, int N, int K)
{
    __shared__ float As[BK][BM];
    __shared__ float Bs[BK][BN];

    const int tid  = threadIdx.x;
    const int row0 = blockIdx.y * BM;
    const int col0 = blockIdx.x * BN;

    // A tile loader: one float4 per thread. arow in [0,128), acol in {0,4}
    const int arow = tid >> 1;
    const int acol = (tid & 1) * 4;
    // B tile loader: one float4 per thread. brow in [0,8), bcol in [0,128) step 4
    const int brow = tid >> 5;
    const int bcol = (tid & 31) * 4;

    const int tx = tid & 15;   // N direction
    const int ty = tid >> 4;   // M direction

    float acc[TM][TN];
    #pragma unroll
    for (int i = 0; i < TM; i++)
        #pragma unroll
        for (int j = 0; j < TN; j++) acc[i][j] = 0.f;

    const float* Aptr = A + (size_t)(row0 + arow) * K + acol;

    // HEADED B addressing precompute
    int hh = 0, dd0 = 0;
    if (HEADED) {
        int n = col0 + bcol;
        hh  = n >> 6;
        dd0 = n & 63;
    }

    for (int k0 = 0; k0 < K; k0 += BK) {
        // ---- load A tile (transposed into As) ----
        float4 av = *(const float4*)(Aptr + k0);
        As[acol + 0][arow] = av.x;
        As[acol + 1][arow] = av.y;
        As[acol + 2][arow] = av.z;
        As[acol + 3][arow] = av.w;

        // ---- load B tile ----
        float4 bv;
        if (HEADED) {
            bv = *(const float4*)(Bm + ((size_t)hh * K + (k0 + brow)) * 64 + dd0);
        } else {
            bv = *(const float4*)(Bm + (size_t)(k0 + brow) * N + col0 + bcol);
        }
        *(float4*)(&Bs[brow][bcol]) = bv;

        __syncthreads();

        #pragma unroll
        for (int kk = 0; kk < BK; kk++) {
            float ar[TM], br[TN];
            #pragma unroll
            for (int i = 0; i < TM; i += 4)
                *(float4*)&ar[i] = *(const float4*)&As[kk][ty * TM + i];
            #pragma unroll
            for (int j = 0; j < TN; j += 4)
                *(float4*)&br[j] = *(const float4*)&Bs[kk][tx * TN + j];
            #pragma unroll
            for (int i = 0; i < TM; i++)
                #pragma unroll
                for (int j = 0; j < TN; j++)
                    acc[i][j] += ar[i] * br[j];
        }
        __syncthreads();
    }

    // ---- epilogue ----
    #pragma unroll
    for (int i = 0; i < TM; i++) {
        const int r = row0 + ty * TM + i;
        float* crow = C + (size_t)r * N;
        const float* rrow = (EPI == 2) ? (res + (size_t)r * N) : nullptr;
        #pragma unroll
        for (int j = 0; j < TN; j += 4) {
            const int c = col0 + tx * TN + j;
            float4 v;
            v.x = acc[i][j + 0];
            v.y = acc[i][j + 1];
            v.z = acc[i][j + 2];
            v.w = acc[i][j + 3];
            if (EPI != 0) {
                float4 bb = *(const float4*)(bias + c);
                v.x += bb.x; v.y += bb.y; v.z += bb.z; v.w += bb.w;
            }
            if (EPI == 2) {
                float4 rv = *(const float4*)(rrow + c);
                v.x += rv.x; v.y += rv.y; v.z += rv.z; v.w += rv.w;
            }
            if (EPI == 1) {
                v.x = fmaxf(v.x, 0.f); v.y = fmaxf(v.y, 0.f);
                v.z = fmaxf(v.z, 0.f); v.w = fmaxf(v.w, 0.f);
            }
            *(float4*)(crow + c) = v;
        }
    }
}

// ---------------------------------------------------------------------------
// Causal flash attention, fp32. Q/K/V/O laid out [B, S, H*D] (token-major).
// One query row per thread, 128 rows per block, 32-key smem tiles.
// scale = E^-0.5 = 1/32 (matches reference: e**-0.5 with e = embedding size).
// ---------------------------------------------------------------------------
#define FBN 32

__global__ void __launch_bounds__(128)
flash_kernel(const float* __restrict__ Q, const float* __restrict__ Kg,
             const float* __restrict__ Vg, float* __restrict__ O)
{
    const int qb = blockIdx.x;          // 0..15  (S / 128)
    const int bh = blockIdx.y;          // 0..63  (B*H)
    const int b  = bh >> 4;
    const int h  = bh & 15;
    const int row = qb * 128 + threadIdx.x;   // global query index within S

    const size_t qoff = ((size_t)(b * Sz + row)) * Ez + h * Dz;

    float4 q4[16];
    {
        const float4* qp = (const float4*)(Q + qoff);
        #pragma unroll
        for (int i = 0; i < 16; i++) q4[i] = qp[i];
        const float scale = 0.03125f;   // 1/sqrt(1024)
        #pragma unroll
        for (int i = 0; i < 16; i++) {
            q4[i].x *= scale; q4[i].y *= scale;
            q4[i].z *= scale; q4[i].w *= scale;
        }
    }

    float4 o4[16];
    #pragma unroll
    for (int i = 0; i < 16; i++) o4[i] = make_float4(0.f, 0.f, 0.f, 0.f);
    float m = -1e9f, l = 0.f;

    __shared__ float Ks[FBN * Dz];
    __shared__ float Vs[FBN * Dz];

    const int nkb = (qb + 1) * (128 / FBN);   // key blocks covering [0, (qb+1)*128)

    for (int kb = 0; kb < nkb; kb++) {
        __syncthreads();
        // cooperative K/V tile load: 32 rows x 64 floats = 512 float4 each
        const size_t kbase = ((size_t)(b * Sz + kb * FBN)) * Ez + h * Dz;
        #pragma unroll
        for (int t = 0; t < 4; t++) {
            const int slot = threadIdx.x + t * 128;  // 0..511
            const int j = slot >> 4, c = slot & 15;
            ((float4*)Ks)[slot] = *(const float4*)(Kg + kbase + (size_t)j * Ez + c * 4);
            ((float4*)Vs)[slot] = *(const float4*)(Vg + kbase + (size_t)j * Ez + c * 4);
        }
        __syncthreads();

        const int jmax = row - kb * FBN;  // valid keys: j <= jmax
        float s[FBN];
        #pragma unroll
        for (int j = 0; j < FBN; j++) {
            const float4* kv = (const float4*)(Ks + j * Dz);
            float a0 = 0.f, a1 = 0.f;
            #pragma unroll
            for (int dd = 0; dd < 16; dd += 2) {
                float4 k0 = kv[dd], k1 = kv[dd + 1];
                a0 += q4[dd].x * k0.x + q4[dd].y * k0.y + q4[dd].z * k0.z + q4[dd].w * k0.w;
                a1 += q4[dd+1].x * k1.x + q4[dd+1].y * k1.y + q4[dd+1].z * k1.z + q4[dd+1].w * k1.w;
            }
            s[j] = (j <= jmax) ? (a0 + a1) : -1e9f;
        }

        float mb = m;
        #pragma unroll
        for (int j = 0; j < FBN; j++) mb = fmaxf(mb, s[j]);
        const float corr = __expf(m - mb);
        m = mb;
        l *= corr;
        #pragma unroll
        for (int i = 0; i < 16; i++) {
            o4[i].x *= corr; o4[i].y *= corr; o4[i].z *= corr; o4[i].w *= corr;
        }

        #pragma unroll
        for (int j = 0; j < FBN; j++) {
            const float p = __expf(s[j] - m);
            l += p;
            const float4* vv = (const float4*)(Vs + j * Dz);
            #pragma unroll
            for (int dd = 0; dd < 16; dd++) {
                float4 v4 = vv[dd];
                o4[dd].x += p * v4.x; o4[dd].y += p * v4.y;
                o4[dd].z += p * v4.z; o4[dd].w += p * v4.w;
            }
        }
    }

    const float inv = 1.f / l;
    float4* op = (float4*)(O + qoff);
    #pragma unroll
    for (int i = 0; i < 16; i++) {
        o4[i].x *= inv; o4[i].y *= inv; o4[i].z *= inv; o4[i].w *= inv;
        op[i] = o4[i];
    }
}

// ---------------------------------------------------------------------------
// Launch
// ---------------------------------------------------------------------------
extern "C" void kernel_launch(void* const* d_in, const int* in_sizes, int n_in,
                              void* d_out, int out_size)
{
    const float* x  = (const float*)d_in[0];
    const float* Wq = (const float*)d_in[1];
    const float* Wk = (const float*)d_in[2];
    const float* Wv = (const float*)d_in[3];
    const float* Wo = (const float*)d_in[4];
    const float* bo = (const float*)d_in[5];
    const float* W1 = (const float*)d_in[6];
    const float* b1 = (const float*)d_in[7];
    const float* W2 = (const float*)d_in[8];
    const float* b2 = (const float*)d_in[9];
    float* out = (float*)d_out;

    float *Qp, *Kp, *Vp, *ATTp, *X1p, *Hp;
    cudaGetSymbolAddress((void**)&Qp,   g_Q);
    cudaGetSymbolAddress((void**)&Kp,   g_K);
    cudaGetSymbolAddress((void**)&Vp,   g_V);
    cudaGetSymbolAddress((void**)&ATTp, g_ATT);
    cudaGetSymbolAddress((void**)&X1p,  g_X1);
    cudaGetSymbolAddress((void**)&Hp,   g_Hb);

    const dim3 blk(256);
    const dim3 grid_e(Ez / BN, Mrows / BM);   // (8, 64)
    const dim3 grid_f(FF / BN, Mrows / BM);   // (32, 64)

    // 1-3: per-head QKV projections (weights in [H,E,D] layout)
    sgemm_kernel<true, 0><<<grid_e, blk>>>(x, Wq, nullptr, nullptr, Qp, Mrows, Ez, Ez);
    sgemm_kernel<true, 0><<<grid_e, blk>>>(x, Wk, nullptr, nullptr, Kp, Mrows, Ez, Ez);
    sgemm_kernel<true, 0><<<grid_e, blk>>>(x, Wv, nullptr, nullptr, Vp, Mrows, Ez, Ez);

    // 4: causal flash attention
    flash_kernel<<<dim3(Sz / 128, Bz * Hz), 128>>>(Qp, Kp, Vp, ATTp);

    // 5: x1 = attn @ Wo + bo + x
    sgemm_kernel<false, 2><<<grid_e, blk>>>(ATTp, Wo, bo, x, X1p, Mrows, Ez, Ez);

    // 6: h = relu(x1 @ W1 + b1)
    sgemm_kernel<false, 1><<<grid_f, blk>>>(X1p, W1, b1, nullptr, Hp, Mrows, FF, Ez);

    // 7: out = x1 + h @ W2 + b2
    sgemm_kernel<false, 2><<<grid_e, blk>>>(Hp, W2, b2, X1p, out, Mrows, Ez, FF);
}